// round 4
// baseline (speedup 1.0000x reference)
#include <cuda_runtime.h>
#include <cuda_bf16.h>

// Problem shape (fixed by the dataset): x (16, 2048, 512) f32, beta (1,), seed int (=0).
// Output: concat(spikes, V), each 16*2048*512 f32.
#define BB 16
#define TT 2048
#define HH 512
#define NC 32            // chunks along T
#define CL 64            // chunk length (NC*CL == TT)
#define NTOT (BB*TT*HH)  // 16777216

// Scratch (allocation-free rule: __device__ globals). float4 type guarantees 16B alignment.
__device__ float4 g_L4[BB*NC*HH/4];
__device__ float4 g_carry4[BB*NC*HH/4];

__device__ __forceinline__ float clampb(float v) {
    return fminf(fmaxf(v, 0.0f), 1.0f);
}

__device__ __forceinline__ unsigned rotl32(unsigned x, int d) {
    return __funnelshift_l(x, x, d);   // one SHF
}

// Exact JAX threefry2x32 (partitionable 32-bit path), key = (k1=0, k2=seed).
// Block input (x0, x1) = (counter_hi = 0, counter_lo = i); output = out0 ^ out1.
// ks0 = k1 = 0, ks1 = seed, ks2 = k1 ^ k2 ^ 0x1BD11BDA = seed ^ 0x1BD11BDA.
__device__ __forceinline__ unsigned tf_bits(unsigned ctr, unsigned ks1, unsigned ks2)
{
    unsigned x0 = 0u;           // 0 + ks0(=0)
    unsigned x1 = ctr + ks1;
#define TFR(r) { x0 += x1; x1 = rotl32(x1, (r)); x1 ^= x0; }
    TFR(13) TFR(15) TFR(26) TFR(6)
    x0 += ks1; x1 += ks2 + 1u;
    TFR(17) TFR(29) TFR(16) TFR(24)
    x0 += ks2; x1 += 2u;              // x1 += ks0 + 2, ks0 = 0
    TFR(13) TFR(15) TFR(26) TFR(6)
    /* x0 += ks0 (=0) */ x1 += ks1 + 3u;
    TFR(17) TFR(29) TFR(16) TFR(24)
    x0 += ks1; x1 += ks2 + 4u;
    TFR(13) TFR(15) TFR(26) TFR(6)
    x0 += ks2; x1 += 5u;              // x1 += ks0 + 5
#undef TFR
    return x0 ^ x1;
}

__device__ __forceinline__ float spike_of(float V, unsigned idx, unsigned ks1, unsigned ks2)
{
    unsigned bits = tf_bits(idx, ks1, ks2);
    // jax uniform: bitcast((bits >> 9) | 0x3f800000) - 1.0  in [0, 1)
    float u = __uint_as_float((bits >> 9) | 0x3f800000u) - 1.0f;
    float z = 10.0f * (V - 1.0f);          // K_SLOPE * (V - THRESHOLD)
    float p = 0.8f / (1.0f + expf(-z));    // MAX_PROB * sigmoid(z), accurate expf
    return (u < p) ? 1.0f : 0.0f;
}

// Thread id decomposition shared by k1/k3: tid -> (b, c, h4)
//   h4 = tid & 127 (float4 column), c = (tid>>7) & 31, b = tid >> 12.  65536 threads total.
// Warp lanes span h4 -> every global access is a contiguous 512B warp transaction.

__global__ void __launch_bounds__(256) k1_local_end(const float* __restrict__ x,
                                                    const float* __restrict__ beta)
{
    int tid = blockIdx.x * blockDim.x + threadIdx.x;
    int h4 = tid & (HH/4 - 1);
    int c  = (tid >> 7) & (NC - 1);
    int b  = tid >> 12;

    float bb  = clampb(beta[0]);
    float omb = 1.0f - bb;

    const float4* xp = reinterpret_cast<const float4*>(x)
                     + (size_t)(b * TT + c * CL) * (HH/4) + h4;
    float4 s = make_float4(0.f, 0.f, 0.f, 0.f);
#pragma unroll 8
    for (int k = 0; k < CL; k++) {
        float4 v = xp[(size_t)k * (HH/4)];
        s.x = fmaf(bb, s.x, omb * v.x);
        s.y = fmaf(bb, s.y, omb * v.y);
        s.z = fmaf(bb, s.z, omb * v.z);
        s.w = fmaf(bb, s.w, omb * v.w);
    }
    g_L4[(b * NC + c) * (HH/4) + h4] = s;
}

__global__ void __launch_bounds__(256) k2_carries(const float* __restrict__ beta)
{
    int tid = blockIdx.x * blockDim.x + threadIdx.x;   // 8192 = BB*HH
    int h = tid & (HH - 1);
    int b = tid >> 9;

    float bb = clampb(beta[0]);
    float pb = bb;
#pragma unroll
    for (int i = 0; i < 6; i++) pb *= pb;              // b^64

    const float* L = reinterpret_cast<const float*>(g_L4);
    float*       C = reinterpret_cast<float*>(g_carry4);
    float acc = 0.0f;
#pragma unroll
    for (int c = 0; c < NC; c++) {
        int idx = (b * NC + c) * HH + h;
        float Lc = L[idx];
        C[idx] = acc;                                  // state entering chunk c
        acc = fmaf(pb, acc, Lc);
    }
}

__global__ void __launch_bounds__(256) k3_scan_spike(const float* __restrict__ x,
                                                     const float* __restrict__ beta,
                                                     const int* __restrict__ seed,
                                                     float* __restrict__ out)
{
    int tid = blockIdx.x * blockDim.x + threadIdx.x;
    int h4 = tid & (HH/4 - 1);
    int c  = (tid >> 7) & (NC - 1);
    int b  = tid >> 12;

    float bb  = clampb(beta[0]);
    float omb = 1.0f - bb;
    unsigned sd  = (unsigned)seed[0];
    unsigned ks1 = sd;
    unsigned ks2 = sd ^ 0x1BD11BDAu;

    float4 s = g_carry4[(b * NC + c) * (HH/4) + h4];
    const float4* xp = reinterpret_cast<const float4*>(x)
                     + (size_t)(b * TT + c * CL) * (HH/4) + h4;
    float* __restrict__ Sout = out;          // spikes: out[0 : N)
    float* __restrict__ Vout = out + NTOT;   // V:      out[N : 2N)
    unsigned base = (unsigned)(b * TT + c * CL) * HH + (unsigned)h4 * 4u;

#pragma unroll 1               // keep body (~5.6KB SASS) inside L0 I$
    for (int k = 0; k < CL; k++) {
        float4 v = xp[(size_t)k * (HH/4)];
        s.x = fmaf(bb, s.x, omb * v.x);
        s.y = fmaf(bb, s.y, omb * v.y);
        s.z = fmaf(bb, s.z, omb * v.z);
        s.w = fmaf(bb, s.w, omb * v.w);

        unsigned i = base + (unsigned)k * HH;
        *reinterpret_cast<float4*>(Vout + i) = s;

        float4 sp;
        sp.x = spike_of(s.x, i + 0u, ks1, ks2);
        sp.y = spike_of(s.y, i + 1u, ks1, ks2);
        sp.z = spike_of(s.z, i + 2u, ks1, ks2);
        sp.w = spike_of(s.w, i + 3u, ks1, ks2);
        *reinterpret_cast<float4*>(Sout + i) = sp;
    }
}

extern "C" void kernel_launch(void* const* d_in, const int* in_sizes, int n_in,
                              void* d_out, int out_size)
{
    const float* x    = (const float*)d_in[0];
    const float* beta = (const float*)d_in[1];
    const int*   seed = (const int*)d_in[2];
    float*       out  = (float*)d_out;

    k1_local_end<<<(BB*NC*(HH/4)) / 256, 256>>>(x, beta);
    k2_carries  <<<(BB*HH) / 256, 256>>>(beta);
    k3_scan_spike<<<(BB*NC*(HH/4)) / 256, 256>>>(x, beta, seed, out);
}

// round 5
// speedup vs baseline: 1.1030x; 1.1030x over previous
#include <cuda_runtime.h>
#include <cuda_bf16.h>

// Problem shape (fixed by the dataset): x (16, 2048, 512) f32, beta (1,), seed int (=0).
// Output: concat(spikes, V), each 16*2048*512 f32.
#define BB 16
#define TT 2048
#define HH 512
#define NC 64            // chunks along T  (R5: 32 -> 64, doubles thread count)
#define CL 32            // chunk length    (R5: 64 -> 32)
#define NTOT (BB*TT*HH)  // 16777216

// Scratch (allocation-free rule: __device__ globals). float4 type guarantees 16B alignment.
__device__ float4 g_L4[BB*NC*HH/4];
__device__ float4 g_carry4[BB*NC*HH/4];

__device__ __forceinline__ float clampb(float v) {
    return fminf(fmaxf(v, 0.0f), 1.0f);
}

__device__ __forceinline__ unsigned rotl32(unsigned x, int d) {
    return __funnelshift_l(x, x, d);   // one SHF
}

// Exact JAX threefry2x32 (partitionable 32-bit path), key = (k1=0, k2=seed).
// Verified bit-exact in R4 (rel_err 1.3e-7 == pure V rounding noise, zero flips).
__device__ __forceinline__ unsigned tf_bits(unsigned ctr, unsigned ks1, unsigned ks2)
{
    unsigned x0 = 0u;           // 0 + ks0(=0)
    unsigned x1 = ctr + ks1;
#define TFR(r) { x0 += x1; x1 = rotl32(x1, (r)); x1 ^= x0; }
    TFR(13) TFR(15) TFR(26) TFR(6)
    x0 += ks1; x1 += ks2 + 1u;
    TFR(17) TFR(29) TFR(16) TFR(24)
    x0 += ks2; x1 += 2u;              // x1 += ks0 + 2, ks0 = 0
    TFR(13) TFR(15) TFR(26) TFR(6)
    /* x0 += ks0 (=0) */ x1 += ks1 + 3u;
    TFR(17) TFR(29) TFR(16) TFR(24)
    x0 += ks1; x1 += ks2 + 4u;
    TFR(13) TFR(15) TFR(26) TFR(6)
    x0 += ks2; x1 += 5u;              // x1 += ks0 + 5
#undef TFR
    return x0 ^ x1;
}

__device__ __forceinline__ float spike_of(float V, unsigned idx, unsigned ks1, unsigned ks2)
{
    unsigned bits = tf_bits(idx, ks1, ks2);
    // jax uniform: bitcast((bits >> 9) | 0x3f800000) - 1.0  in [0, 1)  (exact)
    float u = __uint_as_float((bits >> 9) | 0x3f800000u) - 1.0f;
    // p = 0.8 * sigmoid(10*(V-1)) = 0.8 / (1 + exp(10 - 10V))
    // MUFU.EX2 fast path: exp(a) = exp2(a * log2(e)); |dp| ~ 1e-8 -> ~0.2 expected flips.
    float a = fmaf(-10.0f, V, 10.0f);              // 10 - 10V = -z
    float e = __expf(a);                           // FMUL + MUFU.EX2
    float p = 0.8f / (1.0f + e);                   // FADD + MUFU.RCP + FMUL
    return (u < p) ? 1.0f : 0.0f;
}

// Thread id decomposition shared by k1/k3: tid -> (b, c, h4)
//   h4 = tid & 127 (float4 column), c = (tid>>7) & 63, b = tid >> 13.  131072 threads.
// Warp lanes span h4 -> every global access is a contiguous 512B warp transaction.

__global__ void __launch_bounds__(256) k1_local_end(const float* __restrict__ x,
                                                    const float* __restrict__ beta)
{
    int tid = blockIdx.x * blockDim.x + threadIdx.x;
    int h4 = tid & (HH/4 - 1);
    int c  = (tid >> 7) & (NC - 1);
    int b  = tid >> 13;

    float bb  = clampb(beta[0]);
    float omb = 1.0f - bb;

    const float4* xp = reinterpret_cast<const float4*>(x)
                     + (size_t)(b * TT + c * CL) * (HH/4) + h4;
    float4 s = make_float4(0.f, 0.f, 0.f, 0.f);
#pragma unroll 8
    for (int k = 0; k < CL; k++) {
        float4 v = xp[(size_t)k * (HH/4)];
        s.x = fmaf(bb, s.x, omb * v.x);
        s.y = fmaf(bb, s.y, omb * v.y);
        s.z = fmaf(bb, s.z, omb * v.z);
        s.w = fmaf(bb, s.w, omb * v.w);
    }
    g_L4[(b * NC + c) * (HH/4) + h4] = s;
}

__global__ void __launch_bounds__(256) k2_carries(const float* __restrict__ beta)
{
    int tid = blockIdx.x * blockDim.x + threadIdx.x;   // 8192 = BB*HH
    int h = tid & (HH - 1);
    int b = tid >> 9;

    float bb = clampb(beta[0]);
    float pb = bb;
#pragma unroll
    for (int i = 0; i < 5; i++) pb *= pb;              // b^32 = b^CL

    const float* L = reinterpret_cast<const float*>(g_L4);
    float*       C = reinterpret_cast<float*>(g_carry4);
    float acc = 0.0f;
#pragma unroll
    for (int c = 0; c < NC; c++) {
        int idx = (b * NC + c) * HH + h;
        float Lc = L[idx];
        C[idx] = acc;                                  // state entering chunk c
        acc = fmaf(pb, acc, Lc);
    }
}

__global__ void __launch_bounds__(256) k3_scan_spike(const float* __restrict__ x,
                                                     const float* __restrict__ beta,
                                                     const int* __restrict__ seed,
                                                     float* __restrict__ out)
{
    int tid = blockIdx.x * blockDim.x + threadIdx.x;
    int h4 = tid & (HH/4 - 1);
    int c  = (tid >> 7) & (NC - 1);
    int b  = tid >> 13;

    float bb  = clampb(beta[0]);
    float omb = 1.0f - bb;
    unsigned sd  = (unsigned)seed[0];
    unsigned ks1 = sd;
    unsigned ks2 = sd ^ 0x1BD11BDAu;

    float4 s = g_carry4[(b * NC + c) * (HH/4) + h4];
    const float4* xp = reinterpret_cast<const float4*>(x)
                     + (size_t)(b * TT + c * CL) * (HH/4) + h4;
    float* __restrict__ Sout = out;          // spikes: out[0 : N)
    float* __restrict__ Vout = out + NTOT;   // V:      out[N : 2N)
    unsigned base = (unsigned)(b * TT + c * CL) * HH + (unsigned)h4 * 4u;

#pragma unroll 1               // keep body (~5KB SASS) inside L0 I$
    for (int k = 0; k < CL; k++) {
        float4 v = xp[(size_t)k * (HH/4)];
        s.x = fmaf(bb, s.x, omb * v.x);
        s.y = fmaf(bb, s.y, omb * v.y);
        s.z = fmaf(bb, s.z, omb * v.z);
        s.w = fmaf(bb, s.w, omb * v.w);

        unsigned i = base + (unsigned)k * HH;
        *reinterpret_cast<float4*>(Vout + i) = s;

        float4 sp;
        sp.x = spike_of(s.x, i + 0u, ks1, ks2);
        sp.y = spike_of(s.y, i + 1u, ks1, ks2);
        sp.z = spike_of(s.z, i + 2u, ks1, ks2);
        sp.w = spike_of(s.w, i + 3u, ks1, ks2);
        *reinterpret_cast<float4*>(Sout + i) = sp;
    }
}

extern "C" void kernel_launch(void* const* d_in, const int* in_sizes, int n_in,
                              void* d_out, int out_size)
{
    const float* x    = (const float*)d_in[0];
    const float* beta = (const float*)d_in[1];
    const int*   seed = (const int*)d_in[2];
    float*       out  = (float*)d_out;

    k1_local_end<<<(BB*NC*(HH/4)) / 256, 256>>>(x, beta);
    k2_carries  <<<(BB*HH) / 256, 256>>>(beta);
    k3_scan_spike<<<(BB*NC*(HH/4)) / 256, 256>>>(x, beta, seed, out);
}

// round 6
// speedup vs baseline: 1.2455x; 1.1292x over previous
#include <cuda_runtime.h>
#include <cuda_bf16.h>

// Problem shape (fixed by the dataset): x (16, 2048, 512) f32, beta (1,), seed int (=0).
// Output: concat(spikes, V), each 16*2048*512 f32.
#define BB 16
#define TT 2048
#define HH 512
#define NC 128           // chunks along T  (R6: 64 -> 128)
#define CL 16            // chunk length    (R6: 32 -> 16) => 262144 threads, ~55 warps/SM
#define NTOT (BB*TT*HH)  // 16777216

// Scratch (allocation-free rule: __device__ globals). float4 type guarantees 16B alignment.
__device__ float4 g_L4[BB*NC*HH/4];
__device__ float4 g_carry4[BB*NC*HH/4];

__device__ __forceinline__ float clampb(float v) {
    return fminf(fmaxf(v, 0.0f), 1.0f);
}

__device__ __forceinline__ unsigned rotl32(unsigned x, int d) {
    return __funnelshift_l(x, x, d);   // one SHF
}

// Exact JAX threefry2x32 (partitionable 32-bit path), key = (k1=0, k2=seed).
// Verified bit-exact in R4/R5 (rel_err == pure V f32 rounding noise, zero flips).
__device__ __forceinline__ unsigned tf_bits(unsigned ctr, unsigned ks1, unsigned ks2)
{
    unsigned x0 = 0u;           // 0 + ks0(=0)
    unsigned x1 = ctr + ks1;
#define TFR(r) { x0 += x1; x1 = rotl32(x1, (r)); x1 ^= x0; }
    TFR(13) TFR(15) TFR(26) TFR(6)
    x0 += ks1; x1 += ks2 + 1u;
    TFR(17) TFR(29) TFR(16) TFR(24)
    x0 += ks2; x1 += 2u;              // x1 += ks0 + 2, ks0 = 0
    TFR(13) TFR(15) TFR(26) TFR(6)
    /* x0 += ks0 (=0) */ x1 += ks1 + 3u;
    TFR(17) TFR(29) TFR(16) TFR(24)
    x0 += ks1; x1 += ks2 + 4u;
    TFR(13) TFR(15) TFR(26) TFR(6)
    x0 += ks2; x1 += 5u;              // x1 += ks0 + 5
#undef TFR
    return x0 ^ x1;
}

__device__ __forceinline__ float spike_of(float V, unsigned idx, unsigned ks1, unsigned ks2)
{
    unsigned bits = tf_bits(idx, ks1, ks2);
    // jax uniform: u = bitcast((bits >> 9) | 0x3f800000) - 1.0 in [0,1)  (exact)
    float u = __uint_as_float((bits >> 9) | 0x3f800000u) - 1.0f;
    // spike = u < 0.8/(1+e), e = exp(10-10V).  Division-free equivalent:
    //   u*(1+e) < 0.8  ->  fmaf(u, e, u) < 0.8
    // (boundary shift ~2ulp -> expected flips ~0.2 over all 16.7M elements)
    float a = fmaf(-10.0f, V, 10.0f);              // 10 - 10V
    float e = __expf(a);                           // FMUL + MUFU.EX2
    return (fmaf(u, e, u) < 0.8f) ? 1.0f : 0.0f;   // FFMA + FSETP + SEL
}

// Thread id decomposition shared by k1/k3: tid -> (b, c, h4)
//   h4 = tid & 127 (float4 column), c = (tid>>7) & 127, b = tid >> 14.  262144 threads.
// Warp lanes span h4 -> every global access is a contiguous 512B warp transaction.

__global__ void __launch_bounds__(256) k1_local_end(const float* __restrict__ x,
                                                    const float* __restrict__ beta)
{
    int tid = blockIdx.x * blockDim.x + threadIdx.x;
    int h4 = tid & (HH/4 - 1);
    int c  = (tid >> 7) & (NC - 1);
    int b  = tid >> 14;

    float bb  = clampb(beta[0]);
    float omb = 1.0f - bb;

    const float4* xp = reinterpret_cast<const float4*>(x)
                     + (size_t)(b * TT + c * CL) * (HH/4) + h4;
    float4 s = make_float4(0.f, 0.f, 0.f, 0.f);
#pragma unroll
    for (int k = 0; k < CL; k++) {
        float4 v = xp[(size_t)k * (HH/4)];
        s.x = fmaf(bb, s.x, omb * v.x);
        s.y = fmaf(bb, s.y, omb * v.y);
        s.z = fmaf(bb, s.z, omb * v.z);
        s.w = fmaf(bb, s.w, omb * v.w);
    }
    g_L4[(b * NC + c) * (HH/4) + h4] = s;
}

__global__ void __launch_bounds__(256) k2_carries(const float* __restrict__ beta)
{
    int tid = blockIdx.x * blockDim.x + threadIdx.x;   // 8192 = BB*HH
    int h = tid & (HH - 1);
    int b = tid >> 9;

    float bb = clampb(beta[0]);
    float pb = bb;
#pragma unroll
    for (int i = 0; i < 4; i++) pb *= pb;              // b^16 = b^CL

    const float* L = reinterpret_cast<const float*>(g_L4);
    float*       C = reinterpret_cast<float*>(g_carry4);
    float acc = 0.0f;
#pragma unroll
    for (int c = 0; c < NC; c++) {
        int idx = (b * NC + c) * HH + h;
        float Lc = L[idx];
        C[idx] = acc;                                  // state entering chunk c
        acc = fmaf(pb, acc, Lc);
    }
}

__global__ void __launch_bounds__(256) k3_scan_spike(const float* __restrict__ x,
                                                     const float* __restrict__ beta,
                                                     const int* __restrict__ seed,
                                                     float* __restrict__ out)
{
    int tid = blockIdx.x * blockDim.x + threadIdx.x;
    int h4 = tid & (HH/4 - 1);
    int c  = (tid >> 7) & (NC - 1);
    int b  = tid >> 14;

    float bb  = clampb(beta[0]);
    float omb = 1.0f - bb;
    unsigned sd  = (unsigned)seed[0];
    unsigned ks1 = sd;
    unsigned ks2 = sd ^ 0x1BD11BDAu;

    float4 s = g_carry4[(b * NC + c) * (HH/4) + h4];
    const float4* xp = reinterpret_cast<const float4*>(x)
                     + (size_t)(b * TT + c * CL) * (HH/4) + h4;
    float* __restrict__ Sout = out;          // spikes: out[0 : N)
    float* __restrict__ Vout = out + NTOT;   // V:      out[N : 2N)
    unsigned base = (unsigned)(b * TT + c * CL) * HH + (unsigned)h4 * 4u;

#pragma unroll 1               // keep body (~5KB SASS) inside L0 I$
    for (int k = 0; k < CL; k++) {
        float4 v = xp[(size_t)k * (HH/4)];
        s.x = fmaf(bb, s.x, omb * v.x);
        s.y = fmaf(bb, s.y, omb * v.y);
        s.z = fmaf(bb, s.z, omb * v.z);
        s.w = fmaf(bb, s.w, omb * v.w);

        unsigned i = base + (unsigned)k * HH;
        *reinterpret_cast<float4*>(Vout + i) = s;

        float4 sp;
        sp.x = spike_of(s.x, i + 0u, ks1, ks2);
        sp.y = spike_of(s.y, i + 1u, ks1, ks2);
        sp.z = spike_of(s.z, i + 2u, ks1, ks2);
        sp.w = spike_of(s.w, i + 3u, ks1, ks2);
        *reinterpret_cast<float4*>(Sout + i) = sp;
    }
}

extern "C" void kernel_launch(void* const* d_in, const int* in_sizes, int n_in,
                              void* d_out, int out_size)
{
    const float* x    = (const float*)d_in[0];
    const float* beta = (const float*)d_in[1];
    const int*   seed = (const int*)d_in[2];
    float*       out  = (float*)d_out;

    k1_local_end<<<(BB*NC*(HH/4)) / 256, 256>>>(x, beta);
    k2_carries  <<<(BB*HH) / 256, 256>>>(beta);
    k3_scan_spike<<<(BB*NC*(HH/4)) / 256, 256>>>(x, beta, seed, out);
}